// round 17
// baseline (speedup 1.0000x reference)
#include <cuda_runtime.h>
#include <cuda_fp16.h>
#include <mma.h>
#include <cstdint>

using namespace nvcuda;

#define BB 4
#define NN 8192
#define DD 16
#define RR 32
#define HH 64
#define EE 262144

// Scratch (allocation-free: __device__ globals)
__device__ __half g_P1h[BB * NN * HH];  // fp16: particles @ W1[:16] + b1
__device__ __half g_P2h[BB * NN * HH];  // fp16: particles @ W1[16:]
__device__ float  g_rel[BB * NN * RR];  // per-receiver aggregate (fp32)
__device__ int    g_counts[NN];         // receiver degree histogram
__device__ int    g_offs[NN + 1];       // CSR offsets
__device__ int    g_cursors[NN];        // fill cursors
__device__ int    g_sortedS[EE];        // sender ids, grouped by receiver

// ---------------------------------------------------------------------------
// Prep: histogram receivers, 4 edges/thread (int4 load, 4 atomics in flight)
// ---------------------------------------------------------------------------
__global__ void hist_kernel(const int* __restrict__ receivers) {
    int t = blockIdx.x * 256 + threadIdx.x;
    int4 r4 = ((const int4*)receivers)[t];
    atomicAdd(&g_counts[r4.x], 1);
    atomicAdd(&g_counts[r4.y], 1);
    atomicAdd(&g_counts[r4.z], 1);
    atomicAdd(&g_counts[r4.w], 1);
}

// ---------------------------------------------------------------------------
// Prep: exclusive scan of 8192 counts (single block, 1024 threads)
// ---------------------------------------------------------------------------
__global__ __launch_bounds__(1024) void scan_kernel() {
    __shared__ int sPart[1024];
    int t = threadIdx.x;
    int base = t * 8;
    int c[8], run = 0;
    #pragma unroll
    for (int i = 0; i < 8; i++) {
        int v = g_counts[base + i];
        c[i] = run;           // exclusive within chunk
        run += v;
    }
    sPart[t] = run;
    __syncthreads();
    for (int off = 1; off < 1024; off <<= 1) {
        int v = (t >= off) ? sPart[t - off] : 0;
        __syncthreads();
        sPart[t] += v;
        __syncthreads();
    }
    int prev = (t == 0) ? 0 : sPart[t - 1];
    #pragma unroll
    for (int i = 0; i < 8; i++) {
        int o = prev + c[i];
        g_offs[base + i]    = o;
        g_cursors[base + i] = o;
    }
    if (t == 1023) g_offs[NN] = sPart[1023];
}

// ---------------------------------------------------------------------------
// Prep: fill sorted sender list, 4 edges/thread
// ---------------------------------------------------------------------------
__global__ void fill_kernel(const int* __restrict__ senders,
                            const int* __restrict__ receivers) {
    int t = blockIdx.x * 256 + threadIdx.x;
    int4 r4 = ((const int4*)receivers)[t];
    int4 s4 = ((const int4*)senders)[t];
    int p0 = atomicAdd(&g_cursors[r4.x], 1);
    int p1 = atomicAdd(&g_cursors[r4.y], 1);
    int p2 = atomicAdd(&g_cursors[r4.z], 1);
    int p3 = atomicAdd(&g_cursors[r4.w], 1);
    g_sortedS[p0] = s4.x;
    g_sortedS[p1] = s4.y;
    g_sortedS[p2] = s4.z;
    g_sortedS[p3] = s4.w;
}

// ---------------------------------------------------------------------------
// Kernel A: per-node first-layer projections (fp16 out) + zero histogram.
// TWO threads per (b, n): which=0 computes the P1 row, which=1 the P2 row.
// grid 256 x 256 thr (fills all SMs; was grid 128 @ occ 12%).
// ---------------------------------------------------------------------------
__global__ __launch_bounds__(256) void node_proj_kernel(
    const float* __restrict__ particles,
    const float* __restrict__ W1,   // [32, 64] row-major
    const float* __restrict__ b1)   // [64]
{
    __shared__ float sW1[32 * 64];
    __shared__ float sb1[64];
    for (int i = threadIdx.x; i < 32 * 64; i += 256) sW1[i] = W1[i];
    if (threadIdx.x < 64) sb1[threadIdx.x] = b1[threadIdx.x];
    __syncthreads();

    int gid   = blockIdx.x * 256 + threadIdx.x;  // 0 .. B*N*2-1
    int node  = gid >> 1;
    int which = gid & 1;                         // 0 -> P1, 1 -> P2

    // fold in histogram zeroing (saves a launch)
    if (gid < NN) g_counts[gid] = 0;

    float x[16];
    const float4* xp = (const float4*)(particles + (size_t)node * 16);
    #pragma unroll
    for (int c = 0; c < 4; c++) {
        float4 v = xp[c];
        x[4 * c + 0] = v.x; x[4 * c + 1] = v.y; x[4 * c + 2] = v.z; x[4 * c + 3] = v.w;
    }

    const float* wbase = sW1 + which * 16 * 64;   // rows 0-15 or 16-31
    uint2* outp = (uint2*)((which ? g_P2h : g_P1h) + (size_t)node * 64);

    #pragma unroll
    for (int c = 0; c < 16; c++) {
        float4 acc = which ? make_float4(0.f, 0.f, 0.f, 0.f)
                           : ((const float4*)sb1)[c];
        #pragma unroll
        for (int i = 0; i < 16; i++) {
            float4 w = ((const float4*)(wbase + i * 64))[c];
            acc.x += x[i] * w.x; acc.y += x[i] * w.y;
            acc.z += x[i] * w.z; acc.w += x[i] * w.w;
        }
        __half2 lo = __floats2half2_rn(acc.x, acc.y);
        __half2 hi = __floats2half2_rn(acc.z, acc.w);
        uint2 pkd;
        pkd.x = *reinterpret_cast<unsigned int*>(&lo);
        pkd.y = *reinterpret_cast<unsigned int*>(&hi);
        outp[c] = pkd;
    }
}

// ---------------------------------------------------------------------------
// Kernel B: edge MLP, CSR-by-receiver, ATOMIC-FREE (R16-proven) +
// next-tile sender-id prefetch to hide the per-tile L2 dependent load.
// ---------------------------------------------------------------------------
__global__ __launch_bounds__(256) void edge_kernel(
    const float* __restrict__ W2,   // [64, 32] row-major
    const float* __restrict__ b2)   // [32]
{
    __shared__ __half sW2h[64 * 32];                 // 4KB
    __shared__ __align__(16) char sBuf[8][32 * 144]; // per-warp h/D buffer

    int tid  = threadIdx.x;
    int lane = tid & 31;
    int w    = tid >> 5;

    for (int i = tid; i < 64 * 32; i += 256) sW2h[i] = __float2half(W2[i]);
    __syncthreads();

    int gw = blockIdx.x * 8 + w;        // 0 .. 4*8192-1
    int r  = gw & (NN - 1);
    int b  = gw >> 13;

    const __half* P1b = g_P1h + (size_t)b * NN * 64;
    const __half* P2b = g_P2h + (size_t)b * NN * 64;

    int start = g_offs[r];
    int end   = g_offs[r + 1];

    // P2[r] chunk for this lane (fixed: lane & 7)
    int c = lane & 7;
    uint4 p2c = *((const uint4*)(P2b + (size_t)r * 64) + c);
    float b2j = b2[lane];

    __half* hbuf = (__half*)sBuf[w];    // [32][72] halfs (144B rows)
    float*  dbuf = (float*) sBuf[w];    // [32][36] f32 (aliases hbuf)

    const __half2 z2 = __float2half2_rn(0.f);
    float acc = 0.f;

    int idreg = (start + lane < end) ? g_sortedS[start + lane] : 0;

    for (int tb = start; tb < end; tb += 32) {
        int cnt = min(32, end - tb);

        // ---- gather: 8 insts cover 32 edge rows (4 rows / inst) ----------
        #pragma unroll
        for (int u = 0; u < 8; u++) {
            int esub = u * 4 + (lane >> 3);              // 0..31
            int s = __shfl_sync(0xffffffffu, idreg, esub);
            uint4 v = *((const uint4*)(P1b + (size_t)s * 64) + c);
            __half2 h0 = __hmax2(__hadd2(*reinterpret_cast<__half2*>(&v.x),
                                         *reinterpret_cast<const __half2*>(&p2c.x)), z2);
            __half2 h1 = __hmax2(__hadd2(*reinterpret_cast<__half2*>(&v.y),
                                         *reinterpret_cast<const __half2*>(&p2c.y)), z2);
            __half2 h2 = __hmax2(__hadd2(*reinterpret_cast<__half2*>(&v.z),
                                         *reinterpret_cast<const __half2*>(&p2c.z)), z2);
            __half2 h3 = __hmax2(__hadd2(*reinterpret_cast<__half2*>(&v.w),
                                         *reinterpret_cast<const __half2*>(&p2c.w)), z2);
            uint4 o;
            o.x = *reinterpret_cast<unsigned int*>(&h0);
            o.y = *reinterpret_cast<unsigned int*>(&h1);
            o.z = *reinterpret_cast<unsigned int*>(&h2);
            o.w = *reinterpret_cast<unsigned int*>(&h3);
            *reinterpret_cast<uint4*>((char*)hbuf + esub * 144 + c * 16) = o;
        }
        __syncwarp();

        // ---- prefetch next tile's sender ids (hidden under gemm) ---------
        int idnext = 0;
        {
            int nb = tb + 32;
            if (nb + lane < end) idnext = g_sortedS[nb + lane];
        }

        // ---- gemm: D[32x32] = h[32x64] @ W2[64x32] -----------------------
        wmma::fragment<wmma::accumulator, 16, 16, 16, float> accf[2][2];
        #pragma unroll
        for (int mt = 0; mt < 2; mt++)
            #pragma unroll
            for (int nt = 0; nt < 2; nt++)
                wmma::fill_fragment(accf[mt][nt], 0.0f);

        #pragma unroll
        for (int kt = 0; kt < 4; kt++) {
            wmma::fragment<wmma::matrix_b, 16, 16, 16, __half, wmma::row_major> bf0, bf1;
            wmma::load_matrix_sync(bf0, &sW2h[kt * 16 * 32 + 0], 32);
            wmma::load_matrix_sync(bf1, &sW2h[kt * 16 * 32 + 16], 32);
            #pragma unroll
            for (int mt = 0; mt < 2; mt++) {
                wmma::fragment<wmma::matrix_a, 16, 16, 16, __half, wmma::row_major> af;
                wmma::load_matrix_sync(af, hbuf + mt * 16 * 72 + kt * 16, 72);
                wmma::mma_sync(accf[mt][0], af, bf0, accf[mt][0]);
                wmma::mma_sync(accf[mt][1], af, bf1, accf[mt][1]);
            }
        }
        __syncwarp();

        #pragma unroll
        for (int mt = 0; mt < 2; mt++)
            #pragma unroll
            for (int nt = 0; nt < 2; nt++)
                wmma::store_matrix_sync(dbuf + mt * 16 * 36 + nt * 16,
                                        accf[mt][nt], 36, wmma::mem_row_major);
        __syncwarp();

        // ---- column reduce over valid rows: lane = column ----------------
        {
            float a0 = 0.f, a1 = 0.f, a2 = 0.f, a3 = 0.f;
            int i = 0;
            for (; i + 4 <= cnt; i += 4) {
                a0 += fmaxf(dbuf[(i + 0) * 36 + lane] + b2j, 0.f);
                a1 += fmaxf(dbuf[(i + 1) * 36 + lane] + b2j, 0.f);
                a2 += fmaxf(dbuf[(i + 2) * 36 + lane] + b2j, 0.f);
                a3 += fmaxf(dbuf[(i + 3) * 36 + lane] + b2j, 0.f);
            }
            for (; i < cnt; i++)
                a0 += fmaxf(dbuf[i * 36 + lane] + b2j, 0.f);
            acc += (a0 + a1) + (a2 + a3);
        }
        __syncwarp();   // dbuf reused as hbuf next tile

        idreg = idnext;
    }

    // ---- exclusive ownership: plain coalesced store, NO atomics ----------
    g_rel[((size_t)b * NN + r) * 32 + lane] = acc;
}

// ---------------------------------------------------------------------------
// Kernel C: node MLP + residual. TWO threads per (b, n): each computes half
// of the 64 hidden units + a partial delta[16]; combined via shfl_xor(1);
// each thread stores 8 of the 16 outputs. grid 256 (fills all SMs).
// ---------------------------------------------------------------------------
__global__ __launch_bounds__(256) void node_out_kernel(
    const float* __restrict__ particles,
    const float* __restrict__ W3,   // [48, 64]
    const float* __restrict__ b3,   // [64]
    const float* __restrict__ W4,   // [64, 16]
    const float* __restrict__ b4,   // [16]
    float* __restrict__ out)
{
    __shared__ float sW3[48 * 64];
    __shared__ float sW4[64 * 16];
    __shared__ float sb3[64];
    __shared__ float sb4[16];
    for (int i = threadIdx.x; i < 48 * 64; i += 256) sW3[i] = W3[i];
    for (int i = threadIdx.x; i < 64 * 16; i += 256) sW4[i] = W4[i];
    if (threadIdx.x < 64) sb3[threadIdx.x] = b3[threadIdx.x];
    if (threadIdx.x < 16) sb4[threadIdx.x] = b4[threadIdx.x];
    __syncthreads();

    int gid  = blockIdx.x * 256 + threadIdx.x;   // 0 .. B*N*2-1
    int node = gid >> 1;
    int half = gid & 1;
    int h0   = half * 32;

    float x[48];
    const float4* pp = (const float4*)(particles + (size_t)node * 16);
    #pragma unroll
    for (int c = 0; c < 4; c++) {
        float4 v = pp[c];
        x[4 * c + 0] = v.x; x[4 * c + 1] = v.y; x[4 * c + 2] = v.z; x[4 * c + 3] = v.w;
    }
    const float4* rp = (const float4*)(g_rel + (size_t)node * 32);
    #pragma unroll
    for (int c = 0; c < 8; c++) {
        float4 v = rp[c];
        x[16 + 4 * c + 0] = v.x; x[16 + 4 * c + 1] = v.y;
        x[16 + 4 * c + 2] = v.z; x[16 + 4 * c + 3] = v.w;
    }

    // hidden half: 32 units
    float t[32];
    #pragma unroll
    for (int j = 0; j < 32; j++) t[j] = sb3[h0 + j];

    #pragma unroll
    for (int i = 0; i < 48; i++) {
        const float4* w = (const float4*)(sW3 + i * 64 + h0);
        float xv = x[i];
        #pragma unroll
        for (int j = 0; j < 8; j++) {
            float4 wv = w[j];
            t[4 * j + 0] += xv * wv.x;
            t[4 * j + 1] += xv * wv.y;
            t[4 * j + 2] += xv * wv.z;
            t[4 * j + 3] += xv * wv.w;
        }
    }
    #pragma unroll
    for (int j = 0; j < 32; j++) t[j] = fmaxf(t[j], 0.f);

    // partial delta[16] (half 0 carries the bias)
    float delta[16];
    #pragma unroll
    for (int j = 0; j < 16; j++) delta[j] = half ? 0.f : sb4[j];

    #pragma unroll
    for (int i = 0; i < 32; i++) {
        const float4* w = (const float4*)(sW4 + (h0 + i) * 16);
        float tv = t[i];
        #pragma unroll
        for (int j = 0; j < 4; j++) {
            float4 wv = w[j];
            delta[4 * j + 0] += tv * wv.x;
            delta[4 * j + 1] += tv * wv.y;
            delta[4 * j + 2] += tv * wv.z;
            delta[4 * j + 3] += tv * wv.w;
        }
    }

    // combine partials between the thread pair (lanes differ in bit 0)
    #pragma unroll
    for (int j = 0; j < 16; j++)
        delta[j] += __shfl_xor_sync(0xffffffffu, delta[j], 1);

    // each thread stores 8 of the 16 outputs
    int co = half * 8;
    float4* outp = (float4*)(out + (size_t)node * 16 + co);
    outp[0] = make_float4(x[co + 0] + delta[co + 0], x[co + 1] + delta[co + 1],
                          x[co + 2] + delta[co + 2], x[co + 3] + delta[co + 3]);
    outp[1] = make_float4(x[co + 4] + delta[co + 4], x[co + 5] + delta[co + 5],
                          x[co + 6] + delta[co + 6], x[co + 7] + delta[co + 7]);
}

extern "C" void kernel_launch(void* const* d_in, const int* in_sizes, int n_in,
                              void* d_out, int out_size)
{
    const float* particles = (const float*)d_in[0];
    const int*   senders   = (const int*)d_in[1];
    const int*   receivers = (const int*)d_in[2];
    const float* W1 = (const float*)d_in[3];
    const float* b1 = (const float*)d_in[4];
    const float* W2 = (const float*)d_in[5];
    const float* b2 = (const float*)d_in[6];
    const float* W3 = (const float*)d_in[7];
    const float* b3 = (const float*)d_in[8];
    const float* W4 = (const float*)d_in[9];
    const float* b4 = (const float*)d_in[10];
    float* out = (float*)d_out;

    // proj also zeroes the histogram (hist depends on it, and runs next)
    node_proj_kernel<<<(BB * NN * 2) / 256, 256>>>(particles, W1, b1);

    hist_kernel<<<EE / 1024, 256>>>(receivers);
    scan_kernel<<<1, 1024>>>();
    fill_kernel<<<EE / 1024, 256>>>(senders, receivers);

    edge_kernel<<<(BB * NN) / 8, 256>>>(W2, b2);

    node_out_kernel<<<(BB * NN * 2) / 256, 256>>>(particles, W3, b3, W4, b4, out);
}